// round 2
// baseline (speedup 1.0000x reference)
#include <cuda_runtime.h>
#include <cstddef>

#define NN 13
#define DD 16
#define EPB 16
#define NTHREADS 256
#define NLAYERS 4
#define NCH 4
#define NEG_SLOPE 0.01f
#define BN_EPS 1e-5f
#define ADJF (NCH * NN * NN)   /* 676 floats per element */

// ---------------- constant parameter bank (warp-uniform reads -> LDCU) -----
struct CParams {
  float wi[NN][DD];
  float w0[NLAYERS][DD][DD];
  float b0[NLAYERS][DD];
  float w1[NLAYERS][DD][DD];
  float b1[NLAYERS][DD];
  float fc1[DD][DD]; float fc1b[DD];
  float fc2[DD][DD]; float fc2b[DD];
  float dec[NCH][DD][DD]; float decb[NCH][DD];
  float epsp[NLAYERS];
};

__constant__ CParams c_p;
__device__   CParams d_pack;   // staging buffer (device-writable)

extern "C" __global__ void pack_kernel(
    const float* __restrict__ wi,  const float* __restrict__ eps,
    const float* __restrict__ w0,  const float* __restrict__ b0,
    const float* __restrict__ w1,  const float* __restrict__ b1,
    const float* __restrict__ fc1w, const float* __restrict__ fc1b,
    const float* __restrict__ fc2w, const float* __restrict__ fc2b,
    const float* __restrict__ decw, const float* __restrict__ decb)
{
  const int t = threadIdx.x;
  float* p;
  p = &d_pack.wi[0][0];
  for (int i = t; i < NN * DD; i += NTHREADS) p[i] = wi[i];
  p = &d_pack.w0[0][0][0];
  for (int i = t; i < NLAYERS * DD * DD; i += NTHREADS) p[i] = w0[i];
  p = &d_pack.w1[0][0][0];
  for (int i = t; i < NLAYERS * DD * DD; i += NTHREADS) p[i] = w1[i];
  p = &d_pack.b0[0][0];
  for (int i = t; i < NLAYERS * DD; i += NTHREADS) p[i] = b0[i];
  p = &d_pack.b1[0][0];
  for (int i = t; i < NLAYERS * DD; i += NTHREADS) p[i] = b1[i];
  p = &d_pack.fc1[0][0];
  for (int i = t; i < DD * DD; i += NTHREADS) p[i] = fc1w[i];
  p = &d_pack.fc2[0][0];
  for (int i = t; i < DD * DD; i += NTHREADS) p[i] = fc2w[i];
  if (t < DD) { d_pack.fc1b[t] = fc1b[t]; d_pack.fc2b[t] = fc2b[t]; }
  p = &d_pack.dec[0][0][0];
  for (int i = t; i < NCH * DD * DD; i += NTHREADS) p[i] = decw[i];
  p = &d_pack.decb[0][0];
  for (int i = t; i < NCH * DD; i += NTHREADS) p[i] = decb[i];
  if (t < NLAYERS) d_pack.epsp[t] = eps[t];
}

// ---------------- main kernel ----------------------------------------------
struct Smem {
  float adjr[EPB][ADJF];        // adjacency; reused as recon staging
  float x[EPB][NN][DD];         // node features (reused for decoder temp)
  float bnia[NLAYERS][NN]; float bnib[NLAYERS][NN];
  float bnoa[NLAYERS][NN]; float bnob[NLAYERS][NN];
};

__device__ __forceinline__ float leaky(float v) {
  return v >= 0.f ? v : NEG_SLOPE * v;
}

extern "C" __global__ void __launch_bounds__(NTHREADS, 2)
vae_kernel(const float* __restrict__ g_adj,
           const float* __restrict__ g_big, const float* __restrict__ g_bib,
           const float* __restrict__ g_bim, const float* __restrict__ g_biv,
           const float* __restrict__ g_bog, const float* __restrict__ g_bob,
           const float* __restrict__ g_bom, const float* __restrict__ g_bov,
           float* __restrict__ o_recon, float* __restrict__ o_mu,
           float* __restrict__ o_lv, int Btot)
{
  extern __shared__ unsigned char smem_raw[];
  Smem& s = *reinterpret_cast<Smem*>(smem_raw);
  const int tid = threadIdx.x;

  const int b0blk = blockIdx.x * EPB;
  const int nelem = (Btot - b0blk) < EPB ? (Btot - b0blk) : EPB;

  // ---- stage adjacency (coalesced float4, identity layout [e][676]) ----
  {
    const float4* src = reinterpret_cast<const float4*>(g_adj + (size_t)b0blk * ADJF);
    float4* dst = reinterpret_cast<float4*>(&s.adjr[0][0]);
    const int cnt = nelem * ADJF / 4;
    for (int i = tid; i < cnt; i += NTHREADS) dst[i] = src[i];
  }
  // ---- BN folded affine into smem (lane-indexed, stays off const bank) ----
  for (int i = tid; i < NLAYERS * NN; i += NTHREADS) {
    float a = g_big[i] * rsqrtf(g_biv[i] + BN_EPS);
    (&s.bnia[0][0])[i] = a;
    (&s.bnib[0][0])[i] = g_bib[i] - g_bim[i] * a;
    float ao = g_bog[i] * rsqrtf(g_bov[i] + BN_EPS);
    (&s.bnoa[0][0])[i] = ao;
    (&s.bnob[0][0])[i] = g_bob[i] - g_bom[i] * ao;
  }
  __syncthreads();

  const int e = tid >> 4;          // element within block (half-warp group)
  const int n = tid & 15;          // node index; lanes 13..15 idle
  const bool act = (n < NN) && (e < nelem);
  const unsigned mask = (tid & 16) ? 0xFFFF0000u : 0x0000FFFFu;
  const int b = b0blk + e;

  const float* adjE = &s.adjr[e][0];   // [ch][n][m], ch stride 169, n stride 13

  float x[DD];
  // ---- initial embedding ----
  if (act) {
    #pragma unroll
    for (int d = 0; d < DD; d++) x[d] = 0.f;
    #pragma unroll
    for (int m = 0; m < NN; m++) {
      float am = adjE[0 * 169 + n * NN + m] + adjE[1 * 169 + n * NN + m]
               + adjE[2 * 169 + n * NN + m] + adjE[3 * 169 + n * NN + m];
      #pragma unroll
      for (int d = 0; d < DD; d++) x[d] += am * c_p.wi[m][d];
    }
    float4* xo = reinterpret_cast<float4*>(s.x[e][n]);
    #pragma unroll
    for (int q = 0; q < 4; q++)
      xo[q] = make_float4(x[4*q], x[4*q+1], x[4*q+2], x[4*q+3]);
  }
  __syncwarp(mask);

  // ---- GIN layers (fully unrolled -> immediate const offsets) ----
  #pragma unroll
  for (int l = 0; l < NLAYERS; l++) {
    if (act) {
      float nb[DD];
      #pragma unroll
      for (int d = 0; d < DD; d++) nb[d] = 0.f;
      #pragma unroll
      for (int m = 0; m < NN; m++) {
        float a0 = adjE[0 * 169 + n * NN + m];
        float a1 = adjE[1 * 169 + n * NN + m];
        float a2 = adjE[2 * 169 + n * NN + m];
        float a3 = adjE[3 * 169 + n * NN + m];
        const float4* xm = reinterpret_cast<const float4*>(s.x[e][m]);
        float4 v0 = xm[0], v1 = xm[1], v2 = xm[2], v3 = xm[3];
        nb[0] += a0*v0.x;  nb[1] += a0*v0.y;  nb[2] += a0*v0.z;  nb[3] += a0*v0.w;
        nb[4] += a1*v1.x;  nb[5] += a1*v1.y;  nb[6] += a1*v1.z;  nb[7] += a1*v1.w;
        nb[8] += a2*v2.x;  nb[9] += a2*v2.y;  nb[10]+= a2*v2.z;  nb[11]+= a2*v2.w;
        nb[12]+= a3*v3.x;  nb[13]+= a3*v3.y;  nb[14]+= a3*v3.z;  nb[15]+= a3*v3.w;
      }
      const float ep = 1.f + c_p.epsp[l];
      float agg[DD];
      #pragma unroll
      for (int d = 0; d < DD; d++) agg[d] = ep * x[d] + nb[d];

      const float ai = s.bnia[l][n], bi = s.bnib[l][n];
      float h[DD];
      #pragma unroll
      for (int o = 0; o < DD; o++) {
        float acc = c_p.b0[l][o];
        #pragma unroll
        for (int d = 0; d < DD; d++) acc += agg[d] * c_p.w0[l][o][d];
        h[o] = leaky(acc * ai + bi);
      }
      const float ao = s.bnoa[l][n], bo = s.bnob[l][n];
      #pragma unroll
      for (int o = 0; o < DD; o++) {
        float acc = c_p.b1[l][o];
        #pragma unroll
        for (int d = 0; d < DD; d++) acc += h[d] * c_p.w1[l][o][d];
        x[o] = leaky(acc * ao + bo);
      }
    }
    __syncwarp(mask);   // all group reads of old x done
    if (act) {
      float4* xo = reinterpret_cast<float4*>(s.x[e][n]);
      #pragma unroll
      for (int q = 0; q < 4; q++)
        xo[q] = make_float4(x[4*q], x[4*q+1], x[4*q+2], x[4*q+3]);
    }
    __syncwarp(mask);   // new x visible
  }

  // ---- mu / logvar heads ----
  float mu[DD];
  if (act) {
    float lv[DD];
    #pragma unroll
    for (int o = 0; o < DD; o++) {
      float a1 = c_p.fc1b[o], a2 = c_p.fc2b[o];
      #pragma unroll
      for (int d = 0; d < DD; d++) {
        a1 += x[d] * c_p.fc1[o][d];
        a2 += x[d] * c_p.fc2[o][d];
      }
      mu[o] = a1; lv[o] = a2;
    }
    size_t base = ((size_t)b * NN + n) * DD;
    float4* mo = reinterpret_cast<float4*>(o_mu + base);
    float4* lo = reinterpret_cast<float4*>(o_lv + base);
    #pragma unroll
    for (int q = 0; q < 4; q++) {
      mo[q] = make_float4(mu[4*q], mu[4*q+1], mu[4*q+2], mu[4*q+3]);
      lo[q] = make_float4(lv[4*q], lv[4*q+1], lv[4*q+2], lv[4*q+3]);
    }
  }

  // ---- decoder: stage recon into the (now dead) adj region, then coalesced
  //      block-wide store. Each group only touches its own element's region.
  float* reconE = &s.adjr[e][0];   // reuse: [k][n][m]
  #pragma unroll
  for (int k = 0; k < NCH; k++) {
    float t[DD];
    if (act) {
      #pragma unroll
      for (int d = 0; d < DD; d++) {
        float acc = c_p.decb[k][d];
        #pragma unroll
        for (int l2 = 0; l2 < DD; l2++) acc += mu[l2] * c_p.dec[k][d][l2];
        t[d] = acc;
      }
    }
    __syncwarp(mask);   // previous k's reads of s.x done
    if (act) {
      float4* xo = reinterpret_cast<float4*>(s.x[e][n]);
      #pragma unroll
      for (int q = 0; q < 4; q++)
        xo[q] = make_float4(t[4*q], t[4*q+1], t[4*q+2], t[4*q+3]);
    }
    __syncwarp(mask);
    if (act) {
      float* rp = reconE + (k * NN + n) * NN;
      #pragma unroll
      for (int m = 0; m < NN; m++) {
        const float4* tm = reinterpret_cast<const float4*>(s.x[e][m]);
        float4 v0 = tm[0], v1 = tm[1], v2 = tm[2], v3 = tm[3];
        float acc = t[0]*v0.x + t[1]*v0.y + t[2]*v0.z + t[3]*v0.w
                  + t[4]*v1.x + t[5]*v1.y + t[6]*v1.z + t[7]*v1.w
                  + t[8]*v2.x + t[9]*v2.y + t[10]*v2.z + t[11]*v2.w
                  + t[12]*v3.x + t[13]*v3.y + t[14]*v3.z + t[15]*v3.w;
        rp[m] = fmaxf(acc, 0.f);
      }
    }
  }

  // ---- coalesced recon store for the whole block ----
  __syncthreads();
  {
    const float4* src = reinterpret_cast<const float4*>(&s.adjr[0][0]);
    float4* dst = reinterpret_cast<float4*>(o_recon + (size_t)b0blk * ADJF);
    const int cnt = nelem * ADJF / 4;
    for (int i = tid; i < cnt; i += NTHREADS) dst[i] = src[i];
  }
}

extern "C" void kernel_launch(void* const* d_in, const int* in_sizes, int n_in,
                              void* d_out, int out_size) {
  const float* g_adj  = (const float*)d_in[0];
  const float* g_wi   = (const float*)d_in[1];
  const float* g_eps  = (const float*)d_in[2];
  const float* g_w0   = (const float*)d_in[3];
  const float* g_b0   = (const float*)d_in[4];
  const float* g_w1   = (const float*)d_in[5];
  const float* g_b1   = (const float*)d_in[6];
  const float* g_big  = (const float*)d_in[7];
  const float* g_bib  = (const float*)d_in[8];
  const float* g_bim  = (const float*)d_in[9];
  const float* g_biv  = (const float*)d_in[10];
  const float* g_bog  = (const float*)d_in[11];
  const float* g_bob  = (const float*)d_in[12];
  const float* g_bom  = (const float*)d_in[13];
  const float* g_bov  = (const float*)d_in[14];
  const float* g_fc1w = (const float*)d_in[15];
  const float* g_fc1b = (const float*)d_in[16];
  const float* g_fc2w = (const float*)d_in[17];
  const float* g_fc2b = (const float*)d_in[18];
  const float* g_decw = (const float*)d_in[19];
  const float* g_decb = (const float*)d_in[20];

  const int Btot = in_sizes[0] / ADJF;   // 32768
  float* out = (float*)d_out;
  float* o_recon = out;
  float* o_mu = out + (size_t)Btot * ADJF;
  float* o_lv = o_mu + (size_t)Btot * NN * DD;

  // 1) pack weights into device staging buffer (computations allowed there)
  pack_kernel<<<1, NTHREADS>>>(g_wi, g_eps, g_w0, g_b0, g_w1, g_b1,
                               g_fc1w, g_fc1b, g_fc2w, g_fc2b, g_decw, g_decb);
  // 2) move staging buffer into the constant bank (D2D memcpy node)
  void* packAddr = nullptr;
  cudaGetSymbolAddress(&packAddr, d_pack);
  cudaMemcpyToSymbolAsync(c_p, packAddr, sizeof(CParams), 0,
                          cudaMemcpyDeviceToDevice, 0);

  // 3) main fused kernel
  cudaFuncSetAttribute((const void*)vae_kernel,
                       cudaFuncAttributeMaxDynamicSharedMemorySize,
                       (int)sizeof(Smem));
  int grid = (Btot + EPB - 1) / EPB;
  vae_kernel<<<grid, NTHREADS, sizeof(Smem)>>>(
      g_adj, g_big, g_bib, g_bim, g_biv, g_bog, g_bob, g_bom, g_bov,
      o_recon, o_mu, o_lv, Btot);
}

// round 3
// speedup vs baseline: 1.0741x; 1.0741x over previous
#include <cuda_runtime.h>
#include <cstddef>

#define NN 13
#define DD 16
#define EPB 16
#define NTHREADS 256
#define NLAYERS 4
#define NCH 4
#define BN_EPS 1e-5f
#define ADJF (NCH * NN * NN)   /* 676 floats per element */

typedef unsigned long long u64;

__device__ __forceinline__ u64 pk2(float lo, float hi) {
  u64 r; asm("mov.b64 %0, {%1, %2};" : "=l"(r) : "f"(lo), "f"(hi)); return r;
}
__device__ __forceinline__ u64 bc2(float v) { return pk2(v, v); }
__device__ __forceinline__ u64 fma2(u64 a, u64 b, u64 c) {
  u64 r; asm("fma.rn.f32x2 %0, %1, %2, %3;" : "=l"(r) : "l"(a), "l"(b), "l"(c)); return r;
}
__device__ __forceinline__ u64 mul2(u64 a, u64 b) {
  u64 r; asm("mul.rn.f32x2 %0, %1, %2;" : "=l"(r) : "l"(a), "l"(b)); return r;
}
__device__ __forceinline__ u64 add2(u64 a, u64 b) {
  u64 r; asm("add.rn.f32x2 %0, %1, %2;" : "=l"(r) : "l"(a), "l"(b)); return r;
}
__device__ __forceinline__ float hsum2(u64 v) {
  float lo, hi; asm("mov.b64 {%0, %1}, %2;" : "=f"(lo), "=f"(hi) : "l"(v));
  return lo + hi;
}
__device__ __forceinline__ float leaky(float v) { return fmaxf(v, 0.01f * v); }

struct __align__(16) Smem {
  float adjT[EPB][ADJF];        // [n][m][ch] transposed; reused as recon staging
  float x[EPB][NN][DD];         // node features (reused for decoder temp)
  float w0[NLAYERS][DD][DD];  float b0[NLAYERS][DD];
  float w1[NLAYERS][DD][DD];  float b1[NLAYERS][DD];
  float fc1[DD][DD]; float fc1b[DD];
  float fc2[DD][DD]; float fc2b[DD];
  float dec[NCH][DD][DD]; float decb[NCH][DD];
  float wi[NN][DD];
  float bnia[NLAYERS][NN]; float bnib[NLAYERS][NN];
  float bnoa[NLAYERS][NN]; float bnob[NLAYERS][NN];
  float epsp[NLAYERS];
};

// packed dot16: a2[8] (regs) . row (smem, 16 floats, 16B-aligned)
__device__ __forceinline__ float dot16(const u64* a2, const float* row) {
  const ulonglong2* w = reinterpret_cast<const ulonglong2*>(row);
  ulonglong2 wa = w[0], wb = w[1], wc = w[2], wd = w[3];
  u64 p = mul2(a2[0], wa.x); p = fma2(a2[1], wa.y, p);
  p = fma2(a2[2], wb.x, p);  p = fma2(a2[3], wb.y, p);
  u64 q = mul2(a2[4], wc.x); q = fma2(a2[5], wc.y, q);
  q = fma2(a2[6], wd.x, q);  q = fma2(a2[7], wd.y, q);
  return hsum2(add2(p, q));
}

extern "C" __global__ void __launch_bounds__(NTHREADS, 2)
vae_kernel(const float* __restrict__ g_adj, const float* __restrict__ g_wi,
           const float* __restrict__ g_eps,
           const float* __restrict__ g_w0, const float* __restrict__ g_b0,
           const float* __restrict__ g_w1, const float* __restrict__ g_b1,
           const float* __restrict__ g_big, const float* __restrict__ g_bib,
           const float* __restrict__ g_bim, const float* __restrict__ g_biv,
           const float* __restrict__ g_bog, const float* __restrict__ g_bob,
           const float* __restrict__ g_bom, const float* __restrict__ g_bov,
           const float* __restrict__ g_fc1w, const float* __restrict__ g_fc1b,
           const float* __restrict__ g_fc2w, const float* __restrict__ g_fc2b,
           const float* __restrict__ g_decw, const float* __restrict__ g_decb,
           float* __restrict__ o_recon, float* __restrict__ o_mu,
           float* __restrict__ o_lv, int Btot)
{
  extern __shared__ unsigned char smem_raw[];
  Smem& s = *reinterpret_cast<Smem*>(smem_raw);
  const int tid = threadIdx.x;

  const int b0blk = blockIdx.x * EPB;
  const int nelem = (Btot - b0blk) < EPB ? (Btot - b0blk) : EPB;

  // ---- stage adjacency, transposed to [e][n][m][ch] ----
  {
    const float* src = g_adj + (size_t)b0blk * ADJF;
    const int cnt = nelem * ADJF;
    for (int i = tid; i < cnt; i += NTHREADS) {
      int e = i / ADJF, r = i % ADJF;
      int ch = r / (NN * NN), rr = r % (NN * NN);
      int nr = rr / NN, mr = rr % NN;
      s.adjT[e][(nr * NN + mr) * NCH + ch] = src[i];
    }
  }
  // ---- stage weights / biases (float4 where possible) ----
  {
    float4* dw0 = reinterpret_cast<float4*>(&s.w0[0][0][0]);
    float4* dw1 = reinterpret_cast<float4*>(&s.w1[0][0][0]);
    float4* ddc = reinterpret_cast<float4*>(&s.dec[0][0][0]);
    const float4* sw0 = reinterpret_cast<const float4*>(g_w0);
    const float4* sw1 = reinterpret_cast<const float4*>(g_w1);
    const float4* sdc = reinterpret_cast<const float4*>(g_decw);
    for (int i = tid; i < NLAYERS * DD * DD / 4; i += NTHREADS) {
      dw0[i] = sw0[i]; dw1[i] = sw1[i]; ddc[i] = sdc[i];
    }
    float4* df1 = reinterpret_cast<float4*>(&s.fc1[0][0]);
    float4* df2 = reinterpret_cast<float4*>(&s.fc2[0][0]);
    const float4* sf1 = reinterpret_cast<const float4*>(g_fc1w);
    const float4* sf2 = reinterpret_cast<const float4*>(g_fc2w);
    for (int i = tid; i < DD * DD / 4; i += NTHREADS) { df1[i] = sf1[i]; df2[i] = sf2[i]; }
  }
  for (int i = tid; i < NLAYERS * DD; i += NTHREADS) {
    (&s.b0[0][0])[i]   = g_b0[i];
    (&s.b1[0][0])[i]   = g_b1[i];
    (&s.decb[0][0])[i] = g_decb[i];
  }
  if (tid < DD) { s.fc1b[tid] = g_fc1b[tid]; s.fc2b[tid] = g_fc2b[tid]; }
  for (int i = tid; i < NN * DD; i += NTHREADS) (&s.wi[0][0])[i] = g_wi[i];
  if (tid < NLAYERS) s.epsp[tid] = g_eps[tid];
  for (int i = tid; i < NLAYERS * NN; i += NTHREADS) {
    float a = g_big[i] * rsqrtf(g_biv[i] + BN_EPS);
    (&s.bnia[0][0])[i] = a;
    (&s.bnib[0][0])[i] = g_bib[i] - g_bim[i] * a;
    float ao = g_bog[i] * rsqrtf(g_bov[i] + BN_EPS);
    (&s.bnoa[0][0])[i] = ao;
    (&s.bnob[0][0])[i] = g_bob[i] - g_bom[i] * ao;
  }
  __syncthreads();

  const int e = tid >> 4;
  const int n = tid & 15;
  const bool act = (n < NN) && (e < nelem);
  const unsigned mask = (tid & 16) ? 0xFFFF0000u : 0x0000FFFFu;
  const int b = b0blk + e;

  const float* adjN = &s.adjT[e][n * NN * NCH];   // this node's 13 float4s

  u64 x2[8];
  // ---- initial embedding: x = (sum_ch adj) @ Wi ----
  if (act) {
    #pragma unroll
    for (int j = 0; j < 8; j++) x2[j] = 0ull;
    #pragma unroll
    for (int m = 0; m < NN; m++) {
      float4 a4 = *reinterpret_cast<const float4*>(adjN + m * NCH);
      u64 am = bc2((a4.x + a4.y) + (a4.z + a4.w));
      const ulonglong2* wm = reinterpret_cast<const ulonglong2*>(s.wi[m]);
      ulonglong2 wa = wm[0], wb = wm[1], wc = wm[2], wd = wm[3];
      x2[0] = fma2(am, wa.x, x2[0]); x2[1] = fma2(am, wa.y, x2[1]);
      x2[2] = fma2(am, wb.x, x2[2]); x2[3] = fma2(am, wb.y, x2[3]);
      x2[4] = fma2(am, wc.x, x2[4]); x2[5] = fma2(am, wc.y, x2[5]);
      x2[6] = fma2(am, wd.x, x2[6]); x2[7] = fma2(am, wd.y, x2[7]);
    }
    ulonglong2* xo = reinterpret_cast<ulonglong2*>(s.x[e][n]);
    #pragma unroll
    for (int q = 0; q < 4; q++) xo[q] = make_ulonglong2(x2[2*q], x2[2*q+1]);
  }
  __syncwarp(mask);

  // ---- GIN layers (rolled: keeps I$ small) ----
  #pragma unroll 1
  for (int l = 0; l < NLAYERS; l++) {
    u64 agg2[8];
    if (act) {
      u64 nb[8];
      #pragma unroll
      for (int j = 0; j < 8; j++) nb[j] = 0ull;
      #pragma unroll
      for (int m = 0; m < NN; m++) {
        float4 a4 = *reinterpret_cast<const float4*>(adjN + m * NCH);
        u64 a0 = bc2(a4.x), a1 = bc2(a4.y), a2b = bc2(a4.z), a3 = bc2(a4.w);
        const ulonglong2* xm = reinterpret_cast<const ulonglong2*>(s.x[e][m]);
        ulonglong2 v0 = xm[0], v1 = xm[1], v2 = xm[2], v3 = xm[3];
        nb[0] = fma2(a0, v0.x, nb[0]); nb[1] = fma2(a0, v0.y, nb[1]);
        nb[2] = fma2(a1, v1.x, nb[2]); nb[3] = fma2(a1, v1.y, nb[3]);
        nb[4] = fma2(a2b, v2.x, nb[4]); nb[5] = fma2(a2b, v2.y, nb[5]);
        nb[6] = fma2(a3, v3.x, nb[6]); nb[7] = fma2(a3, v3.y, nb[7]);
      }
      u64 ep = bc2(1.f + s.epsp[l]);
      #pragma unroll
      for (int j = 0; j < 8; j++) agg2[j] = fma2(ep, x2[j], nb[j]);

      const float ai = s.bnia[l][n], bi = s.bnib[l][n];
      float h[DD];
      #pragma unroll
      for (int o = 0; o < DD; o++) {
        float dot = dot16(agg2, s.w0[l][o]) + s.b0[l][o];
        h[o] = leaky(dot * ai + bi);
      }
      u64 h2[8];
      #pragma unroll
      for (int j = 0; j < 8; j++) h2[j] = pk2(h[2*j], h[2*j+1]);

      const float ao = s.bnoa[l][n], bo = s.bnob[l][n];
      float xs[DD];
      #pragma unroll
      for (int o = 0; o < DD; o++) {
        float dot = dot16(h2, s.w1[l][o]) + s.b1[l][o];
        xs[o] = leaky(dot * ao + bo);
      }
      #pragma unroll
      for (int j = 0; j < 8; j++) x2[j] = pk2(xs[2*j], xs[2*j+1]);
    }
    __syncwarp(mask);   // all group reads of old x done
    if (act) {
      ulonglong2* xo = reinterpret_cast<ulonglong2*>(s.x[e][n]);
      #pragma unroll
      for (int q = 0; q < 4; q++) xo[q] = make_ulonglong2(x2[2*q], x2[2*q+1]);
    }
    __syncwarp(mask);   // new x visible
  }

  // ---- mu / logvar heads ----
  float mu[DD];
  u64 mu2[8];
  if (act) {
    float lv[DD];
    #pragma unroll
    for (int o = 0; o < DD; o++) {
      mu[o] = dot16(x2, s.fc1[o]) + s.fc1b[o];
      lv[o] = dot16(x2, s.fc2[o]) + s.fc2b[o];
    }
    #pragma unroll
    for (int j = 0; j < 8; j++) mu2[j] = pk2(mu[2*j], mu[2*j+1]);
    size_t base = ((size_t)b * NN + n) * DD;
    float4* mo = reinterpret_cast<float4*>(o_mu + base);
    float4* lo = reinterpret_cast<float4*>(o_lv + base);
    #pragma unroll
    for (int q = 0; q < 4; q++) {
      mo[q] = make_float4(mu[4*q], mu[4*q+1], mu[4*q+2], mu[4*q+3]);
      lo[q] = make_float4(lv[4*q], lv[4*q+1], lv[4*q+2], lv[4*q+3]);
    }
  }

  // ---- decoder: stage recon into (dead) adjT region, coalesced store after ----
  float* reconE = &s.adjT[e][0];   // reuse: [k][n][m]
  #pragma unroll 1
  for (int k = 0; k < NCH; k++) {
    u64 t2[8];
    if (act) {
      float t[DD];
      #pragma unroll
      for (int d = 0; d < DD; d++)
        t[d] = dot16(mu2, s.dec[k][d]) + s.decb[k][d];
      #pragma unroll
      for (int j = 0; j < 8; j++) t2[j] = pk2(t[2*j], t[2*j+1]);
    }
    __syncwarp(mask);   // previous k's reads of s.x done
    if (act) {
      ulonglong2* xo = reinterpret_cast<ulonglong2*>(s.x[e][n]);
      #pragma unroll
      for (int q = 0; q < 4; q++) xo[q] = make_ulonglong2(t2[2*q], t2[2*q+1]);
    }
    __syncwarp(mask);
    if (act) {
      float* rp = reconE + (k * NN + n) * NN;
      #pragma unroll
      for (int m = 0; m < NN; m++) {
        const ulonglong2* tm = reinterpret_cast<const ulonglong2*>(s.x[e][m]);
        ulonglong2 v0 = tm[0], v1 = tm[1], v2 = tm[2], v3 = tm[3];
        u64 p = mul2(t2[0], v0.x); p = fma2(t2[1], v0.y, p);
        p = fma2(t2[2], v1.x, p);  p = fma2(t2[3], v1.y, p);
        u64 q = mul2(t2[4], v2.x); q = fma2(t2[5], v2.y, q);
        q = fma2(t2[6], v3.x, q);  q = fma2(t2[7], v3.y, q);
        rp[m] = fmaxf(hsum2(add2(p, q)), 0.f);
      }
    }
  }

  // ---- coalesced recon store for the whole block ----
  __syncthreads();
  {
    const float4* src = reinterpret_cast<const float4*>(&s.adjT[0][0]);
    float4* dst = reinterpret_cast<float4*>(o_recon + (size_t)b0blk * ADJF);
    const int cnt = nelem * ADJF / 4;
    for (int i = tid; i < cnt; i += NTHREADS) dst[i] = src[i];
  }
}

extern "C" void kernel_launch(void* const* d_in, const int* in_sizes, int n_in,
                              void* d_out, int out_size) {
  const float* g_adj  = (const float*)d_in[0];
  const float* g_wi   = (const float*)d_in[1];
  const float* g_eps  = (const float*)d_in[2];
  const float* g_w0   = (const float*)d_in[3];
  const float* g_b0   = (const float*)d_in[4];
  const float* g_w1   = (const float*)d_in[5];
  const float* g_b1   = (const float*)d_in[6];
  const float* g_big  = (const float*)d_in[7];
  const float* g_bib  = (const float*)d_in[8];
  const float* g_bim  = (const float*)d_in[9];
  const float* g_biv  = (const float*)d_in[10];
  const float* g_bog  = (const float*)d_in[11];
  const float* g_bob  = (const float*)d_in[12];
  const float* g_bom  = (const float*)d_in[13];
  const float* g_bov  = (const float*)d_in[14];
  const float* g_fc1w = (const float*)d_in[15];
  const float* g_fc1b = (const float*)d_in[16];
  const float* g_fc2w = (const float*)d_in[17];
  const float* g_fc2b = (const float*)d_in[18];
  const float* g_decw = (const float*)d_in[19];
  const float* g_decb = (const float*)d_in[20];

  const int Btot = in_sizes[0] / ADJF;
  float* out = (float*)d_out;
  float* o_recon = out;
  float* o_mu = out + (size_t)Btot * ADJF;
  float* o_lv = o_mu + (size_t)Btot * NN * DD;

  cudaFuncSetAttribute((const void*)vae_kernel,
                       cudaFuncAttributeMaxDynamicSharedMemorySize,
                       (int)sizeof(Smem));
  int grid = (Btot + EPB - 1) / EPB;
  vae_kernel<<<grid, NTHREADS, sizeof(Smem)>>>(
      g_adj, g_wi, g_eps, g_w0, g_b0, g_w1, g_b1,
      g_big, g_bib, g_bim, g_biv, g_bog, g_bob, g_bom, g_bov,
      g_fc1w, g_fc1b, g_fc2w, g_fc2b, g_decw, g_decb,
      o_recon, o_mu, o_lv, Btot);
}

// round 4
// speedup vs baseline: 1.2057x; 1.1225x over previous
#include <cuda_runtime.h>
#include <cstddef>

#define NN 13
#define DD 16
#define EPB 16
#define NTHREADS 128
#define NLAYERS 4
#define NCH 4
#define BN_EPS 1e-5f
#define ADJF (NCH * NN * NN)   /* 676 floats per element */

typedef unsigned long long u64;

__device__ __forceinline__ u64 pk2(float lo, float hi) {
  u64 r; asm("mov.b64 %0, {%1, %2};" : "=l"(r) : "f"(lo), "f"(hi)); return r;
}
__device__ __forceinline__ u64 bc2(float v) { return pk2(v, v); }
__device__ __forceinline__ u64 fma2(u64 a, u64 b, u64 c) {
  u64 r; asm("fma.rn.f32x2 %0, %1, %2, %3;" : "=l"(r) : "l"(a), "l"(b), "l"(c)); return r;
}
__device__ __forceinline__ u64 mul2(u64 a, u64 b) {
  u64 r; asm("mul.rn.f32x2 %0, %1, %2;" : "=l"(r) : "l"(a), "l"(b)); return r;
}
__device__ __forceinline__ u64 add2(u64 a, u64 b) {
  u64 r; asm("add.rn.f32x2 %0, %1, %2;" : "=l"(r) : "l"(a), "l"(b)); return r;
}
__device__ __forceinline__ float hsum2(u64 v) {
  float lo, hi; asm("mov.b64 {%0, %1}, %2;" : "=f"(lo), "=f"(hi) : "l"(v));
  return lo + hi;
}
__device__ __forceinline__ float leaky(float v) { return fmaxf(v, 0.01f * v); }

struct __align__(16) Smem {
  float adj[EPB][NCH][NN][NN];   // identity layout; reused as recon staging
  float x[EPB][NN][DD];          // node features (reused for decoder temp)
  float w0[NLAYERS][DD][DD];  float b0[NLAYERS][DD];
  float w1[NLAYERS][DD][DD];  float b1[NLAYERS][DD];
  float fc1[DD][DD]; float fc1b[DD];
  float fc2[DD][DD]; float fc2b[DD];
  float dec[NCH][DD][DD]; float decb[NCH][DD];
  float wi[NN][DD];
  float bnia[NLAYERS][NN]; float bnib[NLAYERS][NN];
  float bnoa[NLAYERS][NN]; float bnob[NLAYERS][NN];
  float epsp[NLAYERS];
};

// one weight-row load (4x LDS.128 broadcast) feeding TWO packed dot products
__device__ __forceinline__ void dot16x2(const u64* a, const u64* b,
                                        const float* row, float& ra, float& rb) {
  const ulonglong2* w = reinterpret_cast<const ulonglong2*>(row);
  ulonglong2 wa = w[0], wb = w[1], wc = w[2], wd = w[3];
  u64 pa = mul2(a[0], wa.x); pa = fma2(a[1], wa.y, pa);
  pa = fma2(a[2], wb.x, pa); pa = fma2(a[3], wb.y, pa);
  u64 qa = mul2(a[4], wc.x); qa = fma2(a[5], wc.y, qa);
  qa = fma2(a[6], wd.x, qa); qa = fma2(a[7], wd.y, qa);
  ra = hsum2(add2(pa, qa));
  u64 pb = mul2(b[0], wa.x); pb = fma2(b[1], wa.y, pb);
  pb = fma2(b[2], wb.x, pb); pb = fma2(b[3], wb.y, pb);
  u64 qb = mul2(b[4], wc.x); qb = fma2(b[5], wc.y, qb);
  qb = fma2(b[6], wd.x, qb); qb = fma2(b[7], wd.y, qb);
  rb = hsum2(add2(pb, qb));
}

extern "C" __global__ void __launch_bounds__(NTHREADS, 3)
vae_kernel(const float* __restrict__ g_adj, const float* __restrict__ g_wi,
           const float* __restrict__ g_eps,
           const float* __restrict__ g_w0, const float* __restrict__ g_b0,
           const float* __restrict__ g_w1, const float* __restrict__ g_b1,
           const float* __restrict__ g_big, const float* __restrict__ g_bib,
           const float* __restrict__ g_bim, const float* __restrict__ g_biv,
           const float* __restrict__ g_bog, const float* __restrict__ g_bob,
           const float* __restrict__ g_bom, const float* __restrict__ g_bov,
           const float* __restrict__ g_fc1w, const float* __restrict__ g_fc1b,
           const float* __restrict__ g_fc2w, const float* __restrict__ g_fc2b,
           const float* __restrict__ g_decw, const float* __restrict__ g_decb,
           float* __restrict__ o_recon, float* __restrict__ o_mu,
           float* __restrict__ o_lv, int Btot)
{
  extern __shared__ unsigned char smem_raw[];
  Smem& s = *reinterpret_cast<Smem*>(smem_raw);
  const int tid = threadIdx.x;

  const int b0blk = blockIdx.x * EPB;
  const int nelem = (Btot - b0blk) < EPB ? (Btot - b0blk) : EPB;

  // ---- stage adjacency (coalesced float4, identity layout) ----
  {
    const float4* src = reinterpret_cast<const float4*>(g_adj + (size_t)b0blk * ADJF);
    float4* dst = reinterpret_cast<float4*>(&s.adj[0][0][0][0]);
    const int cnt = nelem * ADJF / 4;
    for (int i = tid; i < cnt; i += NTHREADS) dst[i] = src[i];
  }
  // ---- stage weights / biases ----
  {
    float4* dw0 = reinterpret_cast<float4*>(&s.w0[0][0][0]);
    float4* dw1 = reinterpret_cast<float4*>(&s.w1[0][0][0]);
    float4* ddc = reinterpret_cast<float4*>(&s.dec[0][0][0]);
    const float4* sw0 = reinterpret_cast<const float4*>(g_w0);
    const float4* sw1 = reinterpret_cast<const float4*>(g_w1);
    const float4* sdc = reinterpret_cast<const float4*>(g_decw);
    for (int i = tid; i < NLAYERS * DD * DD / 4; i += NTHREADS) {
      dw0[i] = sw0[i]; dw1[i] = sw1[i]; ddc[i] = sdc[i];
    }
    float4* df1 = reinterpret_cast<float4*>(&s.fc1[0][0]);
    float4* df2 = reinterpret_cast<float4*>(&s.fc2[0][0]);
    const float4* sf1 = reinterpret_cast<const float4*>(g_fc1w);
    const float4* sf2 = reinterpret_cast<const float4*>(g_fc2w);
    for (int i = tid; i < DD * DD / 4; i += NTHREADS) { df1[i] = sf1[i]; df2[i] = sf2[i]; }
  }
  for (int i = tid; i < NLAYERS * DD; i += NTHREADS) {
    (&s.b0[0][0])[i]   = g_b0[i];
    (&s.b1[0][0])[i]   = g_b1[i];
    (&s.decb[0][0])[i] = g_decb[i];
  }
  if (tid < DD) { s.fc1b[tid] = g_fc1b[tid]; s.fc2b[tid] = g_fc2b[tid]; }
  for (int i = tid; i < NN * DD; i += NTHREADS) (&s.wi[0][0])[i] = g_wi[i];
  if (tid < NLAYERS) s.epsp[tid] = g_eps[tid];
  for (int i = tid; i < NLAYERS * NN; i += NTHREADS) {
    float a = g_big[i] * rsqrtf(g_biv[i] + BN_EPS);
    (&s.bnia[0][0])[i] = a;
    (&s.bnib[0][0])[i] = g_bib[i] - g_bim[i] * a;
    float ao = g_bog[i] * rsqrtf(g_bov[i] + BN_EPS);
    (&s.bnoa[0][0])[i] = ao;
    (&s.bnob[0][0])[i] = g_bob[i] - g_bom[i] * ao;
  }
  __syncthreads();

  const int grp = tid >> 4;        // 8 groups, each owns TWO elements
  const int n = tid & 15;          // node index; lanes 13..15 idle
  const int e0 = grp * 2, e1 = grp * 2 + 1;
  const bool act = (n < NN);
  const unsigned mask = (tid & 16) ? 0xFFFF0000u : 0x0000FFFFu;
  const int b0g = b0blk + e0, b1g = b0blk + e1;

  u64 xa[8], xb[8];
  // ---- initial embedding for both elements ----
  if (act) {
    #pragma unroll
    for (int j = 0; j < 8; j++) { xa[j] = 0ull; xb[j] = 0ull; }
    #pragma unroll
    for (int m = 0; m < NN; m++) {
      float sa = s.adj[e0][0][n][m] + s.adj[e0][1][n][m]
               + s.adj[e0][2][n][m] + s.adj[e0][3][n][m];
      float sb = s.adj[e1][0][n][m] + s.adj[e1][1][n][m]
               + s.adj[e1][2][n][m] + s.adj[e1][3][n][m];
      u64 ba = bc2(sa), bb = bc2(sb);
      const ulonglong2* wm = reinterpret_cast<const ulonglong2*>(s.wi[m]);
      ulonglong2 wa = wm[0], wbq = wm[1], wc = wm[2], wd = wm[3];
      xa[0]=fma2(ba,wa.x,xa[0]); xa[1]=fma2(ba,wa.y,xa[1]);
      xa[2]=fma2(ba,wbq.x,xa[2]); xa[3]=fma2(ba,wbq.y,xa[3]);
      xa[4]=fma2(ba,wc.x,xa[4]); xa[5]=fma2(ba,wc.y,xa[5]);
      xa[6]=fma2(ba,wd.x,xa[6]); xa[7]=fma2(ba,wd.y,xa[7]);
      xb[0]=fma2(bb,wa.x,xb[0]); xb[1]=fma2(bb,wa.y,xb[1]);
      xb[2]=fma2(bb,wbq.x,xb[2]); xb[3]=fma2(bb,wbq.y,xb[3]);
      xb[4]=fma2(bb,wc.x,xb[4]); xb[5]=fma2(bb,wc.y,xb[5]);
      xb[6]=fma2(bb,wd.x,xb[6]); xb[7]=fma2(bb,wd.y,xb[7]);
    }
    ulonglong2* xo0 = reinterpret_cast<ulonglong2*>(s.x[e0][n]);
    ulonglong2* xo1 = reinterpret_cast<ulonglong2*>(s.x[e1][n]);
    #pragma unroll
    for (int q = 0; q < 4; q++) {
      xo0[q] = make_ulonglong2(xa[2*q], xa[2*q+1]);
      xo1[q] = make_ulonglong2(xb[2*q], xb[2*q+1]);
    }
  }
  __syncwarp(mask);

  // ---- GIN layers ----
  #pragma unroll 1
  for (int l = 0; l < NLAYERS; l++) {
    if (act) {
      u64 na[8], nb[8];
      #pragma unroll
      for (int j = 0; j < 8; j++) { na[j] = 0ull; nb[j] = 0ull; }
      #pragma unroll
      for (int m = 0; m < NN; m++) {
        u64 a0 = bc2(s.adj[e0][0][n][m]), a1 = bc2(s.adj[e0][1][n][m]);
        u64 a2 = bc2(s.adj[e0][2][n][m]), a3 = bc2(s.adj[e0][3][n][m]);
        const ulonglong2* xm0 = reinterpret_cast<const ulonglong2*>(s.x[e0][m]);
        ulonglong2 v0 = xm0[0], v1 = xm0[1], v2 = xm0[2], v3 = xm0[3];
        na[0]=fma2(a0,v0.x,na[0]); na[1]=fma2(a0,v0.y,na[1]);
        na[2]=fma2(a1,v1.x,na[2]); na[3]=fma2(a1,v1.y,na[3]);
        na[4]=fma2(a2,v2.x,na[4]); na[5]=fma2(a2,v2.y,na[5]);
        na[6]=fma2(a3,v3.x,na[6]); na[7]=fma2(a3,v3.y,na[7]);
        u64 c0 = bc2(s.adj[e1][0][n][m]), c1 = bc2(s.adj[e1][1][n][m]);
        u64 c2 = bc2(s.adj[e1][2][n][m]), c3 = bc2(s.adj[e1][3][n][m]);
        const ulonglong2* xm1 = reinterpret_cast<const ulonglong2*>(s.x[e1][m]);
        ulonglong2 u0 = xm1[0], u1 = xm1[1], u2 = xm1[2], u3 = xm1[3];
        nb[0]=fma2(c0,u0.x,nb[0]); nb[1]=fma2(c0,u0.y,nb[1]);
        nb[2]=fma2(c1,u1.x,nb[2]); nb[3]=fma2(c1,u1.y,nb[3]);
        nb[4]=fma2(c2,u2.x,nb[4]); nb[5]=fma2(c2,u2.y,nb[5]);
        nb[6]=fma2(c3,u3.x,nb[6]); nb[7]=fma2(c3,u3.y,nb[7]);
      }
      u64 ep = bc2(1.f + s.epsp[l]);
      #pragma unroll
      for (int j = 0; j < 8; j++) {
        na[j] = fma2(ep, xa[j], na[j]);
        nb[j] = fma2(ep, xb[j], nb[j]);
      }
      const float ai = s.bnia[l][n], bi = s.bnib[l][n];
      float ha[DD], hb[DD];
      #pragma unroll
      for (int o = 0; o < DD; o++) {
        float da, db;
        dot16x2(na, nb, s.w0[l][o], da, db);
        float bias = s.b0[l][o];
        ha[o] = leaky((da + bias) * ai + bi);
        hb[o] = leaky((db + bias) * ai + bi);
      }
      u64 h2a[8], h2b[8];
      #pragma unroll
      for (int j = 0; j < 8; j++) {
        h2a[j] = pk2(ha[2*j], ha[2*j+1]);
        h2b[j] = pk2(hb[2*j], hb[2*j+1]);
      }
      const float ao = s.bnoa[l][n], bo = s.bnob[l][n];
      float sxa[DD], sxb[DD];
      #pragma unroll
      for (int o = 0; o < DD; o++) {
        float da, db;
        dot16x2(h2a, h2b, s.w1[l][o], da, db);
        float bias = s.b1[l][o];
        sxa[o] = leaky((da + bias) * ao + bo);
        sxb[o] = leaky((db + bias) * ao + bo);
      }
      #pragma unroll
      for (int j = 0; j < 8; j++) {
        xa[j] = pk2(sxa[2*j], sxa[2*j+1]);
        xb[j] = pk2(sxb[2*j], sxb[2*j+1]);
      }
    }
    __syncwarp(mask);
    if (act) {
      ulonglong2* xo0 = reinterpret_cast<ulonglong2*>(s.x[e0][n]);
      ulonglong2* xo1 = reinterpret_cast<ulonglong2*>(s.x[e1][n]);
      #pragma unroll
      for (int q = 0; q < 4; q++) {
        xo0[q] = make_ulonglong2(xa[2*q], xa[2*q+1]);
        xo1[q] = make_ulonglong2(xb[2*q], xb[2*q+1]);
      }
    }
    __syncwarp(mask);
  }

  // ---- mu / logvar heads ----
  u64 mua[8], mub[8];
  if (act) {
    float ma[DD], mb[DD], la[DD], lb[DD];
    #pragma unroll
    for (int o = 0; o < DD; o++) {
      float da, db;
      dot16x2(xa, xb, s.fc1[o], da, db);
      ma[o] = da + s.fc1b[o]; mb[o] = db + s.fc1b[o];
      dot16x2(xa, xb, s.fc2[o], da, db);
      la[o] = da + s.fc2b[o]; lb[o] = db + s.fc2b[o];
    }
    #pragma unroll
    for (int j = 0; j < 8; j++) {
      mua[j] = pk2(ma[2*j], ma[2*j+1]);
      mub[j] = pk2(mb[2*j], mb[2*j+1]);
    }
    if (e0 < nelem) {
      size_t base = ((size_t)b0g * NN + n) * DD;
      float4* mo = reinterpret_cast<float4*>(o_mu + base);
      float4* lo = reinterpret_cast<float4*>(o_lv + base);
      #pragma unroll
      for (int q = 0; q < 4; q++) {
        mo[q] = make_float4(ma[4*q], ma[4*q+1], ma[4*q+2], ma[4*q+3]);
        lo[q] = make_float4(la[4*q], la[4*q+1], la[4*q+2], la[4*q+3]);
      }
    }
    if (e1 < nelem) {
      size_t base = ((size_t)b1g * NN + n) * DD;
      float4* mo = reinterpret_cast<float4*>(o_mu + base);
      float4* lo = reinterpret_cast<float4*>(o_lv + base);
      #pragma unroll
      for (int q = 0; q < 4; q++) {
        mo[q] = make_float4(mb[4*q], mb[4*q+1], mb[4*q+2], mb[4*q+3]);
        lo[q] = make_float4(lb[4*q], lb[4*q+1], lb[4*q+2], lb[4*q+3]);
      }
    }
  }

  // ---- decoder: stage recon into (dead) adj region ----
  float* recon0 = &s.adj[e0][0][0][0];
  float* recon1 = &s.adj[e1][0][0][0];
  #pragma unroll 1
  for (int k = 0; k < NCH; k++) {
    u64 ta[8], tb[8];
    if (act) {
      float va[DD], vb[DD];
      #pragma unroll
      for (int d = 0; d < DD; d++) {
        float da, db;
        dot16x2(mua, mub, s.dec[k][d], da, db);
        float bias = s.decb[k][d];
        va[d] = da + bias; vb[d] = db + bias;
      }
      #pragma unroll
      for (int j = 0; j < 8; j++) {
        ta[j] = pk2(va[2*j], va[2*j+1]);
        tb[j] = pk2(vb[2*j], vb[2*j+1]);
      }
    }
    __syncwarp(mask);
    if (act) {
      ulonglong2* xo0 = reinterpret_cast<ulonglong2*>(s.x[e0][n]);
      ulonglong2* xo1 = reinterpret_cast<ulonglong2*>(s.x[e1][n]);
      #pragma unroll
      for (int q = 0; q < 4; q++) {
        xo0[q] = make_ulonglong2(ta[2*q], ta[2*q+1]);
        xo1[q] = make_ulonglong2(tb[2*q], tb[2*q+1]);
      }
    }
    __syncwarp(mask);
    if (act) {
      float* rp0 = recon0 + (k * NN + n) * NN;
      float* rp1 = recon1 + (k * NN + n) * NN;
      #pragma unroll
      for (int m = 0; m < NN; m++) {
        const ulonglong2* tm0 = reinterpret_cast<const ulonglong2*>(s.x[e0][m]);
        ulonglong2 v0 = tm0[0], v1 = tm0[1], v2 = tm0[2], v3 = tm0[3];
        u64 p = mul2(ta[0], v0.x); p = fma2(ta[1], v0.y, p);
        p = fma2(ta[2], v1.x, p);  p = fma2(ta[3], v1.y, p);
        u64 q = mul2(ta[4], v2.x); q = fma2(ta[5], v2.y, q);
        q = fma2(ta[6], v3.x, q);  q = fma2(ta[7], v3.y, q);
        rp0[m] = fmaxf(hsum2(add2(p, q)), 0.f);
        const ulonglong2* tm1 = reinterpret_cast<const ulonglong2*>(s.x[e1][m]);
        ulonglong2 u0 = tm1[0], u1 = tm1[1], u2 = tm1[2], u3 = tm1[3];
        u64 pb = mul2(tb[0], u0.x); pb = fma2(tb[1], u0.y, pb);
        pb = fma2(tb[2], u1.x, pb); pb = fma2(tb[3], u1.y, pb);
        u64 qb = mul2(tb[4], u2.x); qb = fma2(tb[5], u2.y, qb);
        qb = fma2(tb[6], u3.x, qb); qb = fma2(tb[7], u3.y, qb);
        rp1[m] = fmaxf(hsum2(add2(pb, qb)), 0.f);
      }
    }
  }

  // ---- coalesced recon store for the whole block ----
  __syncthreads();
  {
    const float4* src = reinterpret_cast<const float4*>(&s.adj[0][0][0][0]);
    float4* dst = reinterpret_cast<float4*>(o_recon + (size_t)b0blk * ADJF);
    const int cnt = nelem * ADJF / 4;
    for (int i = tid; i < cnt; i += NTHREADS) dst[i] = src[i];
  }
}

extern "C" void kernel_launch(void* const* d_in, const int* in_sizes, int n_in,
                              void* d_out, int out_size) {
  const float* g_adj  = (const float*)d_in[0];
  const float* g_wi   = (const float*)d_in[1];
  const float* g_eps  = (const float*)d_in[2];
  const float* g_w0   = (const float*)d_in[3];
  const float* g_b0   = (const float*)d_in[4];
  const float* g_w1   = (const float*)d_in[5];
  const float* g_b1   = (const float*)d_in[6];
  const float* g_big  = (const float*)d_in[7];
  const float* g_bib  = (const float*)d_in[8];
  const float* g_bim  = (const float*)d_in[9];
  const float* g_biv  = (const float*)d_in[10];
  const float* g_bog  = (const float*)d_in[11];
  const float* g_bob  = (const float*)d_in[12];
  const float* g_bom  = (const float*)d_in[13];
  const float* g_bov  = (const float*)d_in[14];
  const float* g_fc1w = (const float*)d_in[15];
  const float* g_fc1b = (const float*)d_in[16];
  const float* g_fc2w = (const float*)d_in[17];
  const float* g_fc2b = (const float*)d_in[18];
  const float* g_decw = (const float*)d_in[19];
  const float* g_decb = (const float*)d_in[20];

  const int Btot = in_sizes[0] / ADJF;
  float* out = (float*)d_out;
  float* o_recon = out;
  float* o_mu = out + (size_t)Btot * ADJF;
  float* o_lv = o_mu + (size_t)Btot * NN * DD;

  cudaFuncSetAttribute((const void*)vae_kernel,
                       cudaFuncAttributeMaxDynamicSharedMemorySize,
                       (int)sizeof(Smem));
  int grid = (Btot + EPB - 1) / EPB;
  vae_kernel<<<grid, NTHREADS, sizeof(Smem)>>>(
      g_adj, g_wi, g_eps, g_w0, g_b0, g_w1, g_b1,
      g_big, g_bib, g_bim, g_biv, g_bog, g_bob, g_bom, g_bov,
      g_fc1w, g_fc1b, g_fc2w, g_fc2b, g_decw, g_decb,
      o_recon, o_mu, o_lv, Btot);
}